// round 1
// baseline (speedup 1.0000x reference)
#include <cuda_runtime.h>

#define Bsz 64
#define Tlen 1024
#define CHN 256
#define VOC 32000
#define EMB 64
#define LAT 128

// output layout (floats): O_t, c_t, new_h, new_c (tuple order, flattened)
#define OFF_O  0
#define OFF_CT (Bsz*VOC)
#define OFF_H  (OFF_CT + Bsz*CHN)
#define OFF_C  (OFF_H + Bsz*LAT)

// ---- K1: prev_char @ Wc split-K config ----
#define KC1  160
#define NCH1 (VOC / KC1)      // 200 chunks

// ---- K3: attention T-split ----
#define ACH 8
#define TCH (Tlen / ACH)      // 128

// ---- K4: logits GEMM config ----
#define NT   128              // n-tile per block
#define KS   32               // k step staged through smem
#define KTOT (LAT + CHN)      // 384

// -------- device scratch (static globals; no allocation) --------
__device__ float g_part1[NCH1 * Bsz * EMB];   // [chunk][b][e]
__device__ float g_Htfm[Bsz * CHN];
__device__ float g_At[KTOT * Bsz];            // A^T[k][b]: rows 0..127 new_h, 128..383 c_t
__device__ float g_as [Bsz * ACH * CHN];
__device__ float g_aws[Bsz * ACH * CHN];
__device__ float g_logits[Bsz * VOC];

// -------- f32x2 helpers (sm_103a packed fp32) --------
__device__ __forceinline__ unsigned long long dup2(float x) {
    unsigned long long r;
    asm("mov.b64 %0, {%1, %1};" : "=l"(r) : "f"(x));
    return r;
}
__device__ __forceinline__ void ffma2(unsigned long long& acc,
                                      unsigned long long a,
                                      unsigned long long b) {
    asm("fma.rn.f32x2 %0, %1, %2, %0;" : "+l"(acc) : "l"(a), "l"(b));
}
__device__ __forceinline__ void unpack2(unsigned long long v, float& lo, float& hi) {
    asm("mov.b64 {%0, %1}, %2;" : "=f"(lo), "=f"(hi) : "l"(v));
}

// ================= K1: partials of prev_char[64,32000] @ Wc[32000,64] =================
__global__ void k1_char_gemm(const float* __restrict__ prev_char,
                             const float* __restrict__ Wc) {
    __shared__ float Ws[KC1 * EMB];   // 40 KB
    const int chunk = blockIdx.x;
    const int k0 = chunk * KC1;
    for (int i = threadIdx.x; i < KC1 * EMB; i += 256)
        Ws[i] = Wc[k0 * EMB + i];     // Wc chunk is linear: rows k0..k0+159, 64 cols
    __syncthreads();

    const int eq = threadIdx.x & 15;        // 16 e-groups of 4 cols
    const int bq = threadIdx.x >> 4;        // 16 b-groups of 4 rows
    const int e0 = eq * 4, b0 = bq * 4;
    float acc[4][4] = {};
    const float* a0 = prev_char + (size_t)b0 * VOC + k0;
    #pragma unroll 2
    for (int k = 0; k < KC1; k++) {
        float4 w = *(const float4*)&Ws[k * EMB + e0];
        #pragma unroll
        for (int i = 0; i < 4; i++) {
            float a = __ldg(a0 + (size_t)i * VOC + k);
            acc[i][0] = fmaf(a, w.x, acc[i][0]);
            acc[i][1] = fmaf(a, w.y, acc[i][1]);
            acc[i][2] = fmaf(a, w.z, acc[i][2]);
            acc[i][3] = fmaf(a, w.w, acc[i][3]);
        }
    }
    float* out = g_part1 + (size_t)chunk * Bsz * EMB;
    #pragma unroll
    for (int i = 0; i < 4; i++)
        #pragma unroll
        for (int j = 0; j < 4; j++)
            out[(b0 + i) * EMB + e0 + j] = acc[i][j];
}

// ================= K2: reduce partials + Wct1 term, LSTM cell, H_tfm =================
__global__ void k2_lstm(const float* __restrict__ pcv,
                        const float* __restrict__ state_h,
                        const float* __restrict__ state_c,
                        const float* __restrict__ Wct1,
                        const float* __restrict__ lstm_kernel,
                        const float* __restrict__ lstm_rec,
                        const float* __restrict__ W_h,
                        float* __restrict__ d_out) {
    const int b = blockIdx.x;
    const int tid = threadIdx.x;  // 256
    __shared__ float red_s[4][EMB];
    __shared__ float inp_s[EMB];
    __shared__ float h_s[LAT];
    __shared__ float z_s[4 * LAT];
    __shared__ float nh_s[LAT];

    const int e = tid & 63, g = tid >> 6;
    // reduce the 200 split-K partials (fixed order -> deterministic)
    float acc = 0.f;
    for (int c = g; c < NCH1; c += 4)
        acc += g_part1[((size_t)c * Bsz + b) * EMB + e];
    // add prev_cont_vec @ Wct1 (c range split across 4 groups)
    for (int c = g * 64; c < g * 64 + 64; c++)
        acc = fmaf(pcv[b * CHN + c], Wct1[c * EMB + e], acc);
    red_s[g][e] = acc;
    if (tid < LAT) h_s[tid] = state_h[b * LAT + tid];
    __syncthreads();
    if (tid < EMB)
        inp_s[tid] = red_s[0][tid] + red_s[1][tid] + red_s[2][tid] + red_s[3][tid];
    __syncthreads();

    // z = inp @ lstm_kernel + h @ lstm_rec   -> [512]
    for (int j = tid; j < 4 * LAT; j += 256) {
        float z = 0.f;
        for (int ee = 0; ee < EMB; ee++)
            z = fmaf(inp_s[ee], lstm_kernel[ee * 4 * LAT + j], z);
        for (int l = 0; l < LAT; l++)
            z = fmaf(h_s[l], lstm_rec[l * 4 * LAT + j], z);
        z_s[j] = z;
    }
    __syncthreads();

    if (tid < LAT) {
        float zi = z_s[tid], zf = z_s[LAT + tid], zg = z_s[2 * LAT + tid], zo = z_s[3 * LAT + tid];
        float i_ = 1.f / (1.f + __expf(-zi));
        float f_ = 1.f / (1.f + __expf(-zf));
        float gg = tanhf(zg);
        float o_ = 1.f / (1.f + __expf(-zo));
        float nc = fmaf(f_, state_c[b * LAT + tid], i_ * gg);
        float nh = o_ * tanhf(nc);
        nh_s[tid] = nh;
        g_At[tid * Bsz + b] = nh;                       // A^T rows 0..127
        d_out[OFF_H + b * LAT + tid] = nh;
        d_out[OFF_C + b * LAT + tid] = fminf(fmaxf(nc, -10.f), 10.f);
    }
    __syncthreads();

    // H_tfm[b, ch] = new_h @ W_h
    {
        float a2 = 0.f;
        for (int l = 0; l < LAT; l++)
            a2 = fmaf(nh_s[l], W_h[l * CHN + tid], a2);
        g_Htfm[b * CHN + tid] = a2;
    }
}

// ================= K3a: attention partial sums (no-max softmax, |e|<=|V_attn|) =====
__global__ void k3a_attn(const float* __restrict__ F,
                         const float* __restrict__ V_attn) {
    const int chunk = blockIdx.x, b = blockIdx.y;
    const int ch = threadIdx.x;  // 256
    const float h = g_Htfm[b * CHN + ch];
    const float v = V_attn[ch];
    const float* fp = F + ((size_t)b * Tlen + chunk * TCH) * CHN + ch;
    float s = 0.f, ws = 0.f;
    #pragma unroll 4
    for (int t = 0; t < TCH; t++) {
        float f = fp[(size_t)t * CHN];
        float x = h + f;
        // accurate-ish tanh: 1 - 2/(exp(2x)+1)
        float ex = __expf(2.f * x);
        float th = 1.f - __fdividef(2.f, ex + 1.f);
        float p = __expf(v * th);
        s += p;
        ws = fmaf(p, f, ws);
    }
    g_as [(b * ACH + chunk) * CHN + ch] = s;
    g_aws[(b * ACH + chunk) * CHN + ch] = ws;
}

// ================= K3b: merge partials -> c_t =================
__global__ void k3b_merge(float* __restrict__ d_out) {
    const int b = blockIdx.x, ch = threadIdx.x;  // 64 x 256
    float s = 0.f, ws = 0.f;
    #pragma unroll
    for (int c = 0; c < ACH; c++) {
        s  += g_as [(b * ACH + c) * CHN + ch];
        ws += g_aws[(b * ACH + c) * CHN + ch];
    }
    float ct = ws / s;
    d_out[OFF_CT + b * CHN + ch] = ct;
    g_At[(LAT + ch) * Bsz + b] = ct;   // A^T rows 128..383
}

// ================= K4a: logits = [new_h | c_t] @ [Wo ; Wct2]  (f32x2 FMA) =========
__global__ __launch_bounds__(256) void k4a_logits(const float* __restrict__ Wo,
                                                  const float* __restrict__ Wct2) {
    __shared__ float Ws[KS * NT];   // 16 KB
    __shared__ float As[KS * Bsz];  //  8 KB
    const int n0 = blockIdx.x * NT;
    const int tid = threadIdx.x;
    const int nq = tid & 31;        // 32 n-groups of 4 cols
    const int bq = tid >> 5;        //  8 b-groups of 8 rows
    const int nn = n0 + nq * 4;
    const int b0 = bq * 8;

    unsigned long long acc[4][4];   // [b-pair][n] ; pair packs (b even, b odd)
    #pragma unroll
    for (int i = 0; i < 4; i++)
        #pragma unroll
        for (int j = 0; j < 4; j++)
            acc[i][j] = 0ull;

    for (int kb = 0; kb < KTOT / KS; kb++) {
        // stage W tile [KS][NT]
        const bool in_wo = (kb * KS) < LAT;
        for (int i = tid; i < KS * NT; i += 256) {
            int kl = i >> 7, col = i & 127;
            int kg = kb * KS + kl;
            Ws[i] = in_wo ? Wo[(size_t)kg * VOC + n0 + col]
                          : Wct2[(size_t)(kg - LAT) * VOC + n0 + col];
        }
        // stage A^T tile [KS][64] (linear copy)
        for (int i = tid; i < KS * Bsz; i += 256)
            As[i] = g_At[(size_t)kb * KS * Bsz + i];
        __syncthreads();

        #pragma unroll 4
        for (int kl = 0; kl < KS; kl++) {
            ulonglong2 aA = *(const ulonglong2*)&As[kl * Bsz + b0];
            ulonglong2 aB = *(const ulonglong2*)&As[kl * Bsz + b0 + 4];
            float4 w = *(const float4*)&Ws[kl * NT + nq * 4];
            unsigned long long wd0 = dup2(w.x), wd1 = dup2(w.y),
                               wd2 = dup2(w.z), wd3 = dup2(w.w);
            ffma2(acc[0][0], aA.x, wd0); ffma2(acc[0][1], aA.x, wd1);
            ffma2(acc[0][2], aA.x, wd2); ffma2(acc[0][3], aA.x, wd3);
            ffma2(acc[1][0], aA.y, wd0); ffma2(acc[1][1], aA.y, wd1);
            ffma2(acc[1][2], aA.y, wd2); ffma2(acc[1][3], aA.y, wd3);
            ffma2(acc[2][0], aB.x, wd0); ffma2(acc[2][1], aB.x, wd1);
            ffma2(acc[2][2], aB.x, wd2); ffma2(acc[2][3], aB.x, wd3);
            ffma2(acc[3][0], aB.y, wd0); ffma2(acc[3][1], aB.y, wd1);
            ffma2(acc[3][2], aB.y, wd2); ffma2(acc[3][3], aB.y, wd3);
        }
        __syncthreads();
    }

    #pragma unroll
    for (int bp = 0; bp < 4; bp++) {
        #pragma unroll
        for (int n = 0; n < 4; n++) {
            float lo, hi;
            unpack2(acc[bp][n], lo, hi);
            int b = b0 + bp * 2;
            g_logits[(size_t)b * VOC + nn + n] = lo;
            g_logits[(size_t)(b + 1) * VOC + nn + n] = hi;
        }
    }
}

// ================= K4b: row softmax over V -> O_t =================
__global__ void k4b_softmax(float* __restrict__ d_out) {
    const int b = blockIdx.x;
    const int tid = threadIdx.x;  // 256
    __shared__ float red[256];
    const float* lg = g_logits + (size_t)b * VOC;

    float m = -1e30f;
    for (int i = tid; i < VOC; i += 256) m = fmaxf(m, lg[i]);
    red[tid] = m; __syncthreads();
    for (int st = 128; st > 0; st >>= 1) {
        if (tid < st) red[tid] = fmaxf(red[tid], red[tid + st]);
        __syncthreads();
    }
    m = red[0]; __syncthreads();

    float s = 0.f;
    for (int i = tid; i < VOC; i += 256) s += __expf(lg[i] - m);
    red[tid] = s; __syncthreads();
    for (int st = 128; st > 0; st >>= 1) {
        if (tid < st) red[tid] += red[tid + st];
        __syncthreads();
    }
    float inv = 1.f / red[0];

    for (int i = tid; i < VOC; i += 256)
        d_out[OFF_O + (size_t)b * VOC + i] = __expf(lg[i] - m) * inv;
}

// ================= launch =================
extern "C" void kernel_launch(void* const* d_in, const int* in_sizes, int n_in,
                              void* d_out_v, int out_size) {
    const float* pcv       = (const float*)d_in[0];
    const float* F         = (const float*)d_in[1];
    const float* prev_char = (const float*)d_in[2];
    const float* state_h   = (const float*)d_in[3];
    const float* state_c   = (const float*)d_in[4];
    const float* Wc        = (const float*)d_in[5];
    const float* Wct1      = (const float*)d_in[6];
    const float* Wo        = (const float*)d_in[7];
    const float* Wct2      = (const float*)d_in[8];
    const float* lk        = (const float*)d_in[9];
    const float* lr        = (const float*)d_in[10];
    const float* Wh        = (const float*)d_in[11];
    const float* Va        = (const float*)d_in[12];
    float* d_out = (float*)d_out_v;

    k1_char_gemm<<<NCH1, 256>>>(prev_char, Wc);
    k2_lstm<<<Bsz, 256>>>(pcv, state_h, state_c, Wct1, lk, lr, Wh, d_out);
    k3a_attn<<<dim3(ACH, Bsz), 256>>>(F, Va);
    k3b_merge<<<Bsz, CHN>>>(d_out);
    k4a_logits<<<VOC / NT, 256>>>(Wo, Wct2);
    k4b_softmax<<<Bsz, 256>>>(d_out);
}

// round 4
// speedup vs baseline: 1.1216x; 1.1216x over previous
#include <cuda_runtime.h>

#define Bsz 64
#define Tlen 1024
#define CHN 256
#define VOC 32000
#define EMB 64
#define LAT 128

// output layout (floats): O_t, c_t, new_h, new_c (tuple order, flattened)
#define OFF_O  0
#define OFF_CT (Bsz*VOC)
#define OFF_H  (OFF_CT + Bsz*CHN)
#define OFF_C  (OFF_H + Bsz*LAT)

// ---- K1: prev_char @ Wc split-K config ----
#define KC1  160
#define NCH1 (VOC / KC1)      // 200 chunks

// ---- K3: attention T-split ----
#define ACH 8
#define TCH (Tlen / ACH)      // 128

// ---- K4: logits GEMM config ----
#define NT4  256              // n-tile per block
#define KS4  16               // k rows staged per tile
#define KTOT (LAT + CHN)      // 384
#define NBLK4 (VOC / NT4)     // 125 blocks (single wave)

// -------- device scratch (static globals; no allocation) --------
__device__ float g_part1[NCH1 * Bsz * EMB];   // [chunk][b][e]
__device__ float g_Htfm[Bsz * CHN];
__device__ float g_At[KTOT * Bsz];            // A^T[k][b]: rows 0..127 new_h, 128..383 c_t
__device__ float g_as [Bsz * ACH * CHN];
__device__ float g_aws[Bsz * ACH * CHN];
__device__ float g_logits[Bsz * VOC];         // holds exp(logit) after k4a
__device__ float g_psum[NBLK4 * Bsz];         // per-(ntile,b) partial exp sums

// -------- f32x2 helpers (sm_103a packed fp32) --------
__device__ __forceinline__ void ffma2(unsigned long long& acc,
                                      unsigned long long a,
                                      unsigned long long b) {
    asm("fma.rn.f32x2 %0, %1, %2, %0;" : "+l"(acc) : "l"(a), "l"(b));
}
__device__ __forceinline__ void fadd2(unsigned long long& acc, unsigned long long o) {
    asm("add.rn.f32x2 %0, %0, %1;" : "+l"(acc) : "l"(o));
}
__device__ __forceinline__ void unpack2(unsigned long long v, float& lo, float& hi) {
    asm("mov.b64 {%0, %1}, %2;" : "=f"(lo), "=f"(hi) : "l"(v));
}
__device__ __forceinline__ float tanhfast(float x) {
    float y; asm("tanh.approx.f32 %0, %1;" : "=f"(y) : "f"(x)); return y;
}

// ================= K1: partials of prev_char[64,32000] @ Wc[32000,64] =================
__global__ void k1_char_gemm(const float* __restrict__ prev_char,
                             const float* __restrict__ Wc) {
    __shared__ float Ws[KC1 * EMB];   // 40 KB
    const int chunk = blockIdx.x;
    const int k0 = chunk * KC1;
    for (int i = threadIdx.x; i < KC1 * EMB; i += 256)
        Ws[i] = Wc[k0 * EMB + i];
    __syncthreads();

    const int eq = threadIdx.x & 15;        // 16 e-groups of 4 cols
    const int bq = threadIdx.x >> 4;        // 16 b-groups of 4 rows
    const int e0 = eq * 4, b0 = bq * 4;
    float acc[4][4] = {};
    const float* a0 = prev_char + (size_t)b0 * VOC + k0;
    #pragma unroll 2
    for (int k = 0; k < KC1; k++) {
        float4 w = *(const float4*)&Ws[k * EMB + e0];
        #pragma unroll
        for (int i = 0; i < 4; i++) {
            float a = __ldg(a0 + (size_t)i * VOC + k);
            acc[i][0] = fmaf(a, w.x, acc[i][0]);
            acc[i][1] = fmaf(a, w.y, acc[i][1]);
            acc[i][2] = fmaf(a, w.z, acc[i][2]);
            acc[i][3] = fmaf(a, w.w, acc[i][3]);
        }
    }
    float* out = g_part1 + (size_t)chunk * Bsz * EMB;
    #pragma unroll
    for (int i = 0; i < 4; i++)
        #pragma unroll
        for (int j = 0; j < 4; j++)
            out[(b0 + i) * EMB + e0 + j] = acc[i][j];
}

// ================= K2: reduce partials + Wct1 term, LSTM cell, H_tfm =================
__global__ void k2_lstm(const float* __restrict__ pcv,
                        const float* __restrict__ state_h,
                        const float* __restrict__ state_c,
                        const float* __restrict__ Wct1,
                        const float* __restrict__ lstm_kernel,
                        const float* __restrict__ lstm_rec,
                        const float* __restrict__ W_h,
                        float* __restrict__ d_out) {
    const int b = blockIdx.x;
    const int tid = threadIdx.x;  // 256
    __shared__ float red_s[4][EMB];
    __shared__ float inp_s[EMB];
    __shared__ float h_s[LAT];
    __shared__ float z_s[4 * LAT];
    __shared__ float nh_s[LAT];

    const int e = tid & 63, g = tid >> 6;
    float acc = 0.f;
    for (int c = g; c < NCH1; c += 4)
        acc += g_part1[((size_t)c * Bsz + b) * EMB + e];
    for (int c = g * 64; c < g * 64 + 64; c++)
        acc = fmaf(pcv[b * CHN + c], Wct1[c * EMB + e], acc);
    red_s[g][e] = acc;
    if (tid < LAT) h_s[tid] = state_h[b * LAT + tid];
    __syncthreads();
    if (tid < EMB)
        inp_s[tid] = red_s[0][tid] + red_s[1][tid] + red_s[2][tid] + red_s[3][tid];
    __syncthreads();

    for (int j = tid; j < 4 * LAT; j += 256) {
        float z = 0.f;
        for (int ee = 0; ee < EMB; ee++)
            z = fmaf(inp_s[ee], lstm_kernel[ee * 4 * LAT + j], z);
        for (int l = 0; l < LAT; l++)
            z = fmaf(h_s[l], lstm_rec[l * 4 * LAT + j], z);
        z_s[j] = z;
    }
    __syncthreads();

    if (tid < LAT) {
        float zi = z_s[tid], zf = z_s[LAT + tid], zg = z_s[2 * LAT + tid], zo = z_s[3 * LAT + tid];
        float i_ = 1.f / (1.f + __expf(-zi));
        float f_ = 1.f / (1.f + __expf(-zf));
        float gg = tanhf(zg);
        float o_ = 1.f / (1.f + __expf(-zo));
        float nc = fmaf(f_, state_c[b * LAT + tid], i_ * gg);
        float nh = o_ * tanhf(nc);
        nh_s[tid] = nh;
        g_At[tid * Bsz + b] = nh;
        d_out[OFF_H + b * LAT + tid] = nh;
        d_out[OFF_C + b * LAT + tid] = fminf(fmaxf(nc, -10.f), 10.f);
    }
    __syncthreads();

    {
        float a2 = 0.f;
        for (int l = 0; l < LAT; l++)
            a2 = fmaf(nh_s[l], W_h[l * CHN + tid], a2);
        g_Htfm[b * CHN + tid] = a2;
    }
}

// ================= K3a: attention partial sums (no-max softmax, |e|<=|V_attn|) =====
__global__ void k3a_attn(const float* __restrict__ F,
                         const float* __restrict__ V_attn) {
    const int chunk = blockIdx.x, b = blockIdx.y;
    const int ch = threadIdx.x;  // 256
    const float h = g_Htfm[b * CHN + ch];
    const float v = V_attn[ch];
    const float* fp = F + ((size_t)b * Tlen + chunk * TCH) * CHN + ch;
    float s = 0.f, ws = 0.f;
    #pragma unroll 8
    for (int t = 0; t < TCH; t++) {
        float f = fp[(size_t)t * CHN];
        float p = __expf(v * tanhfast(h + f));
        s += p;
        ws = fmaf(p, f, ws);
    }
    g_as [(b * ACH + chunk) * CHN + ch] = s;
    g_aws[(b * ACH + chunk) * CHN + ch] = ws;
}

// ================= K3b: merge partials -> c_t =================
__global__ void k3b_merge(float* __restrict__ d_out) {
    const int b = blockIdx.x, ch = threadIdx.x;  // 64 x 256
    float s = 0.f, ws = 0.f;
    #pragma unroll
    for (int c = 0; c < ACH; c++) {
        s  += g_as [(b * ACH + c) * CHN + ch];
        ws += g_aws[(b * ACH + c) * CHN + ch];
    }
    float ct = ws / s;
    d_out[OFF_CT + b * CHN + ch] = ct;
    g_At[(LAT + ch) * Bsz + b] = ct;   // A^T rows 128..383
}

// ================= K4a: exp(logits) + per-tile softmax partial sums ================
// logits = [new_h | c_t] @ [Wo ; Wct2] via f32x2 FMA.
// 125 blocks (single wave), 256 threads = (nq:32) x (bq:4) x (kq:2 split-K halves).
// Per thread: 8 b-pairs (16 b) x 8 n-cols, cols interleaved by lane (conflict-free).
__global__ __launch_bounds__(256) void k4a_logits(const float* __restrict__ Wo,
                                                  const float* __restrict__ Wct2) {
    __shared__ float2 Wd[KS4 * NT4];   // W duplicated pairs, 32 KB
    __shared__ float  As[KS4 * Bsz];   // A^T tile, 4 KB
    const int tid = threadIdx.x;
    const int nq = tid & 31;
    const int bq = (tid >> 5) & 3;
    const int kq = tid >> 7;
    const int n0 = blockIdx.x * NT4;

    unsigned long long acc[64];        // [pair p:8][col c:8]
    #pragma unroll
    for (int i = 0; i < 64; i++) acc[i] = 0ull;

    for (int kb = 0; kb < KTOT / KS4; kb++) {
        __syncthreads();
        const float* Wsrc = (kb * KS4 < LAT)
            ? (Wo   + (size_t)(kb * KS4) * VOC + n0)
            : (Wct2 + (size_t)(kb * KS4 - LAT) * VOC + n0);
        #pragma unroll
        for (int it = 0; it < (KS4 * NT4) / 256; it++) {
            int i = tid + it * 256;
            int r = i >> 8, c = i & 255;
            float w = Wsrc[(size_t)r * VOC + c];
            Wd[r * NT4 + c] = make_float2(w, w);
        }
        #pragma unroll
        for (int it = 0; it < (KS4 * Bsz) / 256; it++) {
            int i = tid + it * 256;
            As[i] = g_At[kb * KS4 * Bsz + i];
        }
        __syncthreads();

        #pragma unroll
        for (int klh = 0; klh < KS4 / 2; klh++) {
            const int kl = kq * (KS4 / 2) + klh;
            unsigned long long a[8], w[8];
            const float* ap = As + kl * Bsz + bq * 16;
            #pragma unroll
            for (int i = 0; i < 4; i++) {
                ulonglong2 t = *(const ulonglong2*)(ap + i * 4);  // broadcast within warp
                a[2 * i] = t.x; a[2 * i + 1] = t.y;
            }
            const float2* wp = Wd + kl * NT4 + nq;                // lane-consecutive
            #pragma unroll
            for (int j = 0; j < 8; j++)
                w[j] = *(const unsigned long long*)(wp + 32 * j);
            #pragma unroll
            for (int p = 0; p < 8; p++)
                #pragma unroll
                for (int c = 0; c < 8; c++)
                    ffma2(acc[p * 8 + c], a[p], w[c]);
        }
    }

    // combine the two split-K halves (reuse Wd as u64 buffer, transposed layout)
    __syncthreads();
    unsigned long long* buf = (unsigned long long*)Wd;  // 4096 u64 capacity
    #pragma unroll
    for (int ch2 = 0; ch2 < 2; ch2++) {
        if (kq == 1) {
            #pragma unroll
            for (int j = 0; j < 32; j++)
                buf[j * 128 + (tid - 128)] = acc[ch2 * 32 + j];
        }
        __syncthreads();
        if (kq == 0) {
            #pragma unroll
            for (int j = 0; j < 32; j++)
                fadd2(acc[ch2 * 32 + j], buf[j * 128 + tid]);
        }
        __syncthreads();
    }

    if (kq == 0) {  // warps 0..3, full warps -> shfl safe
        float bsum[16];
        #pragma unroll
        for (int j = 0; j < 16; j++) bsum[j] = 0.f;
        #pragma unroll
        for (int p = 0; p < 8; p++) {
            const int b = bq * 16 + 2 * p;
            #pragma unroll
            for (int c = 0; c < 8; c++) {
                float lo, hi;
                unpack2(acc[p * 8 + c], lo, hi);
                float e0 = __expf(lo), e1 = __expf(hi);   // logits tiny: no max needed
                const int col = n0 + nq + 32 * c;
                g_logits[(size_t)b * VOC + col] = e0;
                g_logits[(size_t)(b + 1) * VOC + col] = e1;
                bsum[2 * p]     += e0;
                bsum[2 * p + 1] += e1;
            }
        }
        #pragma unroll
        for (int j = 0; j < 16; j++) {
            #pragma unroll
            for (int o = 16; o > 0; o >>= 1)
                bsum[j] += __shfl_xor_sync(0xffffffffu, bsum[j], o);
        }
        if (nq == 0) {
            #pragma unroll
            for (int j = 0; j < 16; j++)
                g_psum[blockIdx.x * Bsz + bq * 16 + j] = bsum[j];
        }
    }
}

// ================= K4b: normalize -> O_t ================
__global__ void k4b_scale(float* __restrict__ d_out) {
    const int sl = blockIdx.x, b = blockIdx.y;   // grid (8, 64)
    const int tid = threadIdx.x;                 // 256
    __shared__ float red[128];
    if (tid < 128) red[tid] = (tid < NBLK4) ? g_psum[tid * Bsz + b] : 0.f;
    __syncthreads();
    for (int s = 64; s > 0; s >>= 1) {
        if (tid < s) red[tid] += red[tid + s];
        __syncthreads();
    }
    const float inv = 1.f / red[0];
    const size_t base = (size_t)b * VOC + sl * (VOC / 8);
    for (int i = tid; i < VOC / 8; i += 256)
        d_out[OFF_O + base + i] = g_logits[base + i] * inv;
}

// ================= launch =================
extern "C" void kernel_launch(void* const* d_in, const int* in_sizes, int n_in,
                              void* d_out_v, int out_size) {
    const float* pcv       = (const float*)d_in[0];
    const float* F         = (const float*)d_in[1];
    const float* prev_char = (const float*)d_in[2];
    const float* state_h   = (const float*)d_in[3];
    const float* state_c   = (const float*)d_in[4];
    const float* Wc        = (const float*)d_in[5];
    const float* Wct1      = (const float*)d_in[6];
    const float* Wo        = (const float*)d_in[7];
    const float* Wct2      = (const float*)d_in[8];
    const float* lk        = (const float*)d_in[9];
    const float* lr        = (const float*)d_in[10];
    const float* Wh        = (const float*)d_in[11];
    const float* Va        = (const float*)d_in[12];
    float* d_out = (float*)d_out_v;

    k1_char_gemm<<<NCH1, 256>>>(prev_char, Wc);
    k2_lstm<<<Bsz, 256>>>(pcv, state_h, state_c, Wct1, lk, lr, Wh, d_out);
    k3a_attn<<<dim3(ACH, Bsz), 256>>>(F, Va);
    k3b_merge<<<Bsz, CHN>>>(d_out);
    k4a_logits<<<NBLK4, 256>>>(Wo, Wct2);
    k4b_scale<<<dim3(8, Bsz), 256>>>(d_out);
}